// round 15
// baseline (speedup 1.0000x reference)
#include <cuda_runtime.h>
#include <cuda_fp16.h>
#include <stdint.h>

// ============================ problem constants ============================
#define F_DIM   39
#define NT      256
#define MT      64               // rows (b,d) per CTA = 2 batch elems
#define NCH0    24
#define NCH12   78
#define NCHT    (NCH0 + 2*NCH12) // 180
#define K0_REAL 1521
#define K12     4992

// weights: fp16, fragment order (verified R10-R14):
// 16B unit idx = ((s*16 + gp)*32 + lane)
__device__ __align__(256) uint4 g_B[(size_t)NCHT * 2048];

// ============================ smem layout (bytes) ==========================
#define B_BUF  32768                     // 2 buffers
#define SM_B   0
#define AS     36                        // A row stride in 4B words (144B)
#define A_BUF  (MT*AS*4)                 // 9216, 2 buffers
#define SM_A   (2*B_BUF)                 // 65536
#define SM_X   (SM_A + 2*A_BUF)          // 83968 : x fp32 [64][XS]
#define XS     41
#define HS2    136                       // h fp16 row stride (halfs)
#define SM_H   (SM_X + MT*XS*4)          // 94464 : h fp16 [64][HS2]
#define SM_RS  (SM_H + MT*HS2*2)         // 111872: rowsum[64]
#define SM_MB  (SM_RS + 256)             // 112128: 2 mbarriers
#define SM_TOT (SM_MB + 64)              // 112192  (x2 CTAs < 228KB)

// ============================ helpers ======================================
__device__ __forceinline__ uint32_t s2u(const void* p) {
    uint32_t a;
    asm("{ .reg .u64 t; cvta.to.shared.u64 t, %1; cvt.u32.u64 %0, t; }" : "=r"(a) : "l"(p));
    return a;
}
#define MB_INIT(mb, c) asm volatile("mbarrier.init.shared.b64 [%0], %1;" :: "r"(mb), "r"(c) : "memory")

#define MB_WAIT(mb, par) do {                                                   \
    uint32_t _m = (mb), _p = (par), _d;                                         \
    asm volatile("{ .reg .pred p; mbarrier.try_wait.parity.shared.b64 p, [%1], %2; selp.b32 %0,1,0,p; }" \
        : "=r"(_d) : "r"(_m), "r"(_p) : "memory");                              \
    if (!_d) {                                                                  \
        asm volatile("{ .reg .pred P1; WL%=: mbarrier.try_wait.parity.shared.b64 P1, [%0], %1; @P1 bra.uni WD%=; bra.uni WL%=; WD%=: }" \
            :: "r"(_m), "r"(_p) : "memory");                                    \
    }                                                                           \
} while (0)

__device__ __forceinline__ void bulk_ld(uint32_t dst, const void* src, uint32_t bytes, uint32_t mb) {
    asm volatile("mbarrier.arrive.expect_tx.shared.b64 _, [%0], %1;" :: "r"(mb), "r"(bytes) : "memory");
    asm volatile("cp.async.bulk.shared::cluster.global.mbarrier::complete_tx::bytes [%0], [%1], %2, [%3];"
        :: "r"(dst), "l"(src), "r"(bytes), "r"(mb) : "memory");
}

__device__ __forceinline__ void mma_f16(float* c, const uint32_t* a, uint32_t b0, uint32_t b1) {
    asm volatile("mma.sync.aligned.m16n8k16.row.col.f32.f16.f16.f32 "
        "{%0,%1,%2,%3}, {%4,%5,%6,%7}, {%8,%9}, {%0,%1,%2,%3};"
        : "+f"(c[0]), "+f"(c[1]), "+f"(c[2]), "+f"(c[3])
        : "r"(a[0]), "r"(a[1]), "r"(a[2]), "r"(a[3]), "r"(b0), "r"(b1));
}
__device__ __forceinline__ void lds128(uint32_t& r0, uint32_t& r1, uint32_t& r2, uint32_t& r3, uint32_t a) {
    asm volatile("ld.shared.v4.u32 {%0,%1,%2,%3}, [%4];"
        : "=r"(r0), "=r"(r1), "=r"(r2), "=r"(r3) : "r"(a));
}
__device__ __forceinline__ void ldmx4(uint32_t* r, uint32_t a) {
    asm volatile("ldmatrix.sync.aligned.m8n8.x4.shared.b16 {%0,%1,%2,%3}, [%4];"
        : "=r"(r[0]), "=r"(r[1]), "=r"(r[2]), "=r"(r[3]) : "r"(a));
}

// ================= weight shuffle kernel (fragment order) ==================
__global__ void conv_kernel(const float* __restrict__ W, int Kreal, int chunk0) {
    extern __shared__ float ws[];     // [64][257]
    const int lc = blockIdx.x, tid = threadIdx.x;
    for (int i = 0; i < 64; i++) {
        int k = lc * 64 + i;
        ws[i * 257 + tid] = (k < Kreal) ? W[(size_t)k * 256 + tid] : 0.f;
    }
    __syncthreads();
    const size_t base = (size_t)(chunk0 + lc) * 2048;
    for (int u = tid; u < 2048; u += 256) {
        int lane = u & 31, gp = (u >> 5) & 15, s = (u >> 9) & 3;
        int kb = s * 16 + (lane & 3) * 2;
        uint32_t wreg[4];
#pragma unroll
        for (int e = 0; e < 2; e++) {
            int n = (gp * 2 + e) * 8 + (lane >> 2);
            __half2 w0 = __floats2half2_rn(ws[kb * 257 + n],       ws[(kb + 1) * 257 + n]);
            __half2 w1 = __floats2half2_rn(ws[(kb + 8) * 257 + n], ws[(kb + 9) * 257 + n]);
            wreg[e * 2]     = *(uint32_t*)&w0;
            wreg[e * 2 + 1] = *(uint32_t*)&w1;
        }
        g_B[base + u] = make_uint4(wreg[0], wreg[1], wreg[2], wreg[3]);
    }
}

// =============== cooperative A generation: fp16 into SMEM ==================
// thread tid -> row m = tid/4, k-quarter kq = tid&3 (16 k each = 8 half2)
__device__ __forceinline__ void gen_A0(
    const float* __restrict__ xsm, uint32_t* __restrict__ Asm,
    int lch, int tid)
{
    const int m = tid >> 2;
    const int k0 = lch * 64 + (tid & 3) * 16;
    int f = k0 / F_DIM, c = k0 - f * F_DIM;
    const float* xrow = xsm + m * XS;
    uint32_t w8[8];
    float xa = xrow[f];
#pragma unroll
    for (int w = 0; w < 8; w++) {
        const int k = k0 + w * 2;
        float a0 = (k < K0_REAL) ? xa * xrow[c] : 0.f;
        if (++c == F_DIM) { c = 0; xa = xrow[++f]; }
        float a1 = (k + 1 < K0_REAL) ? xa * xrow[c] : 0.f;
        if (++c == F_DIM) { c = 0; xa = xrow[++f]; }
        __half2 p = __floats2half2_rn(a0, a1);
        w8[w] = *(uint32_t*)&p;
    }
    uint4* dst = (uint4*)(Asm + m * AS + (tid & 3) * 8);
    dst[0] = make_uint4(w8[0], w8[1], w8[2], w8[3]);
    dst[1] = make_uint4(w8[4], w8[5], w8[6], w8[7]);
}

__device__ __forceinline__ void gen_A12(
    const float* __restrict__ xsm, const __half* __restrict__ hsm,
    uint32_t* __restrict__ Asm, int lch, int tid)
{
    const int m = tid >> 2;
    const int k0 = lch * 64 + (tid & 3) * 16;
    const int f = k0 >> 7, c0 = k0 & 127;
    const float xa = xsm[m * XS + f];
    const uint4* hrow = (const uint4*)(hsm + m * HS2 + c0);
    uint4* dst = (uint4*)(Asm + m * AS + (tid & 3) * 8);
#pragma unroll
    for (int half16 = 0; half16 < 2; half16++) {
        uint4 hv = hrow[half16];
        uint32_t hw[4] = { hv.x, hv.y, hv.z, hv.w };
        uint32_t ow[4];
#pragma unroll
        for (int e = 0; e < 4; e++) {
            float2 hf = __half22float2(*(__half2*)&hw[e]);
            __half2 p = __floats2half2_rn(xa * hf.x, xa * hf.y);
            ow[e] = *(uint32_t*)&p;
        }
        dst[half16] = make_uint4(ow[0], ow[1], ow[2], ow[3]);
    }
}

// =================== per-chunk MMA, s-range [S0,S1) =======================
// warp grid 2M x 4N: wm in [0,2) -> 32-row tile (2 mt x 16);
//                    wn in [0,4) -> 64-col tile
template<int S0, int S1>
__device__ __forceinline__ void chunk_mma_part(
    uint32_t abase, uint32_t bbuf, int lane, int wm, int wn,
    float (&acc)[2][8][4])
{
    const int mtx = lane >> 3, rw = lane & 7;
    const uint32_t alane = abase
        + (uint32_t)((wm * 32 + rw + (mtx & 1) * 8) * 144)
        + (uint32_t)((mtx >> 1) * 16);
    const uint32_t blane = bbuf + (uint32_t)(wn * 2048 + lane * 16);

#pragma unroll
    for (int s = S0; s < S1; s++) {
        uint32_t bfr[4][4], afr[2][4];
#pragma unroll
        for (int g = 0; g < 4; g++)
            lds128(bfr[g][0], bfr[g][1], bfr[g][2], bfr[g][3],
                   blane + s * 8192 + g * 512);
#pragma unroll
        for (int mt = 0; mt < 2; mt++)
            ldmx4(afr[mt], alane + s * 32 + mt * (16 * 144));
#pragma unroll
        for (int g = 0; g < 4; g++)
#pragma unroll
            for (int e = 0; e < 2; e++)
#pragma unroll
                for (int mt = 0; mt < 2; mt++)
                    mma_f16(acc[mt][g * 2 + e], afr[mt],
                            bfr[g][e * 2], bfr[g][e * 2 + 1]);
    }
}

// ============================ main fused kernel ============================
__global__ void __launch_bounds__(NT, 2)
cin_mma(const float* __restrict__ x,
        const float* __restrict__ b0, const float* __restrict__ b1,
        const float* __restrict__ b2,
        const float* __restrict__ fcw, const float* __restrict__ fcb,
        float* __restrict__ out)
{
    extern __shared__ char sm[];
    const uint32_t smb = s2u(sm);
    float* xsm = (float*)(sm + SM_X);
    __half* hsm = (__half*)(sm + SM_H);
    float* rowsum = (float*)(sm + SM_RS);

    const int tid = threadIdx.x, wid = tid >> 5, lane = tid & 31;
    const int wm = wid & 1, wn = wid >> 1;
    const int m0 = blockIdx.x * MT;

    if (tid < MT) rowsum[tid] = 0.f;
    if (tid == 0) { MB_INIT(smb + SM_MB, 1); MB_INIT(smb + SM_MB + 8, 1); }

    // stage x tile: xsm[ml][f] = x[b, f, d];  m = m0+ml
    for (int i = tid; i < F_DIM * MT; i += NT) {
        int f = i >> 6, ml = i & 63, m = m0 + ml;
        xsm[ml * XS + f] = x[((size_t)(m >> 5) * F_DIM + f) * 32 + (m & 31)];
    }
    __syncthreads();    // x ready, mbarriers visible

    auto stage = [&](int gch) {
        if (tid == 0)
            bulk_ld(smb + SM_B + (gch & 1) * B_BUF, g_B + (size_t)gch * 2048, B_BUF,
                    smb + SM_MB + (gch & 1) * 8);
    };
    auto abuf = [&](int gch) -> uint32_t* {
        return (uint32_t*)(sm + SM_A + (gch & 1) * A_BUF);
    };

    float acc[2][8][4];
    uint32_t ph[2] = {0, 0};
    int gch = 0;
    stage(0);

    for (int L = 0; L < 3; L++) {
        const int nch = (L == 0) ? NCH0 : NCH12;
#pragma unroll
        for (int mt = 0; mt < 2; mt++)
#pragma unroll
            for (int j = 0; j < 8; j++)
#pragma unroll
                for (int r = 0; r < 4; r++) acc[mt][j][r] = 0.f;

        // gen A for this layer's FIRST chunk (h ready after prior epilogue)
        if (L == 0) gen_A0(xsm, abuf(gch), 0, tid);
        else        gen_A12(xsm, hsm, abuf(gch), 0, tid);

        for (int lch = 0; lch < nch; lch++, gch++) {
            const int q = gch & 1;
            const uint32_t ab = smb + SM_A + q * A_BUF;
            const uint32_t bb = smb + SM_B + q * B_BUF;

            MB_WAIT(smb + SM_MB + q * 8, ph[q]);
            ph[q] ^= 1;
            __syncthreads();    // A(gch) visible; all warps done chunk gch-1
                                // => B/A buffers of parity (gch+1)&1 are free
            if (gch + 1 < NCHT) stage(gch + 1);

            chunk_mma_part<0, 2>(ab, bb, lane, wm, wn, acc);

            // gen A for next chunk of SAME layer while s=0,1 MMAs drain
            if (lch + 1 < nch) {
                if (L == 0) gen_A0(xsm, abuf(gch + 1), lch + 1, tid);
                else        gen_A12(xsm, hsm, abuf(gch + 1), lch + 1, tid);
            }

            chunk_mma_part<2, 4>(ab, bb, lane, wm, wn, acc);
            // no trailing barrier; next chunk's sync re-converges
        }

        // ---- layer epilogue: bias+relu, h feedback (fp16), fc_w dots ----
        const float* bias = (L == 0) ? b0 : (L == 1) ? b1 : b2;
        const float* fa   = (L == 0) ? (fcw - 128) : (L == 1) ? fcw : (fcw + 256);
        const int cs      = (L < 2) ? 128 : 0;
        const bool wh     = (L < 2);
        float rs[4] = {0.f, 0.f, 0.f, 0.f};
#pragma unroll
        for (int mt = 0; mt < 2; mt++)
#pragma unroll
            for (int j = 0; j < 8; j++)
#pragma unroll
                for (int r = 0; r < 4; r++) {
                    int row = wm * 32 + mt * 16 + (lane >> 2) + ((r >> 1) << 3);
                    int col = wn * 64 + j * 8 + ((lane & 3) << 1) + (r & 1);
                    float v = fmaxf(acc[mt][j][r] + __ldg(&bias[col]), 0.f);
                    if (wh && col < 128) hsm[row * HS2 + col] = __float2half(v);
                    if (col >= cs) rs[mt * 2 + (r >> 1)] += v * __ldg(&fa[col]);
                }
#pragma unroll
        for (int i = 0; i < 4; i++) {
            float v = rs[i];
            v += __shfl_xor_sync(0xffffffffu, v, 1);
            v += __shfl_xor_sync(0xffffffffu, v, 2);
            if ((lane & 3) == 0) {
                int row = wm * 32 + (i >> 1) * 16 + (lane >> 2) + ((i & 1) << 3);
                atomicAdd(&rowsum[row], v);
            }
        }
        __syncthreads();    // h + rowsum complete before next layer's gen
    }

    // final: each 32-row group (= one batch element) reduces to one scalar
    if (tid < MT) {
        float v = rowsum[tid];
#pragma unroll
        for (int o = 16; o; o >>= 1) v += __shfl_xor_sync(0xffffffffu, v, o);
        if ((tid & 31) == 0) out[blockIdx.x * 2 + wid] = v + fcb[0];
    }
}

// ============================ launch =======================================
extern "C" void kernel_launch(void* const* d_in, const int* in_sizes, int n_in,
                              void* d_out, int out_size)
{
    const float* x   = (const float*)d_in[0];
    const float* W0  = (const float*)d_in[1];
    const float* b0  = (const float*)d_in[2];
    const float* W1  = (const float*)d_in[3];
    const float* b1  = (const float*)d_in[4];
    const float* W2  = (const float*)d_in[5];
    const float* b2  = (const float*)d_in[6];
    const float* fcw = (const float*)d_in[7];
    const float* fcb = (const float*)d_in[8];
    float* out = (float*)d_out;

    // weight shuffle/convert (every launch; idempotent, graph-capturable)
    const int conv_smem = 64 * 257 * 4;
    cudaFuncSetAttribute(conv_kernel, cudaFuncAttributeMaxDynamicSharedMemorySize, conv_smem);
    conv_kernel<<<NCH0,  256, conv_smem>>>(W0, K0_REAL, 0);
    conv_kernel<<<NCH12, 256, conv_smem>>>(W1, K12, NCH0);
    conv_kernel<<<NCH12, 256, conv_smem>>>(W2, K12, NCH0 + NCH12);

    int B = in_sizes[0] / (F_DIM * 32);      // 1024
    int grid = (B * 32) / MT;                // 512

    cudaFuncSetAttribute(cin_mma, cudaFuncAttributeMaxDynamicSharedMemorySize, SM_TOT);
    cin_mma<<<grid, NT, SM_TOT>>>(x, b0, b1, b2, fcw, fcb, out);
}

// round 16
// speedup vs baseline: 1.0065x; 1.0065x over previous
#include <cuda_runtime.h>
#include <cuda_fp16.h>
#include <stdint.h>

// ============================ problem constants ============================
#define F_DIM   39
#define NT      256
#define MT      64               // rows (b,d) per CTA = 2 batch elems
#define K0_REAL 1521
// K128 chunks: layer0 1536/128=12, layers1/2 4992/128=39
#define NCH0    12
#define NCH12   39
#define NCHT    (NCH0 + 2*NCH12) // 90

// weights: fp16, fragment order, K128 chunks of 4096 uint4 units:
// unit idx within chunk = ((s*16 + gp)*32 + lane), s in [0,8)
//   n = (2*gp + e)*8 + lane/4,  k_in_chunk = s*16 + (lane%4)*2 (+1,+8,+9)
__device__ __align__(256) uint4 g_B[(size_t)NCHT * 4096];

// ============================ smem layout (bytes) ==========================
#define AS     68                        // A row stride in 4B words (272B)
#define A_BUF  (MT*AS*4)                 // 17408, 2 buffers
#define SM_A   0
#define SM_X   (2*A_BUF)                 // 34816 : x fp32 [64][XS]
#define XS     41
#define HS2    136                       // h fp16 row stride (halfs)
#define SM_H   (SM_X + MT*XS*4)          // 45312 : h fp16 [64][HS2]
#define SM_RS  (SM_H + MT*HS2*2)         // 62720 : rowsum[64]
#define SM_TOT (SM_RS + 256)             // 62976

// ============================ helpers ======================================
__device__ __forceinline__ uint32_t s2u(const void* p) {
    uint32_t a;
    asm("{ .reg .u64 t; cvta.to.shared.u64 t, %1; cvt.u32.u64 %0, t; }" : "=r"(a) : "l"(p));
    return a;
}
__device__ __forceinline__ void mma_f16(float* c, const uint32_t* a, uint32_t b0, uint32_t b1) {
    asm volatile("mma.sync.aligned.m16n8k16.row.col.f32.f16.f16.f32 "
        "{%0,%1,%2,%3}, {%4,%5,%6,%7}, {%8,%9}, {%0,%1,%2,%3};"
        : "+f"(c[0]), "+f"(c[1]), "+f"(c[2]), "+f"(c[3])
        : "r"(a[0]), "r"(a[1]), "r"(a[2]), "r"(a[3]), "r"(b0), "r"(b1));
}
__device__ __forceinline__ void ldmx4(uint32_t* r, uint32_t a) {
    asm volatile("ldmatrix.sync.aligned.m8n8.x4.shared.b16 {%0,%1,%2,%3}, [%4];"
        : "=r"(r[0]), "=r"(r[1]), "=r"(r[2]), "=r"(r[3]) : "r"(a));
}

// ================= weight shuffle kernel (fragment order) ==================
// each block handles 64 k-rows; two blocks fill one K128 chunk.
// chunk0 is in K128-chunk units.
__global__ void conv_kernel(const float* __restrict__ W, int Kreal, int chunk0) {
    extern __shared__ float ws[];     // [64][257]
    const int lc = blockIdx.x, tid = threadIdx.x;
    for (int i = 0; i < 64; i++) {
        int k = lc * 64 + i;
        ws[i * 257 + tid] = (k < Kreal) ? W[(size_t)k * 256 + tid] : 0.f;
    }
    __syncthreads();
    const size_t base = (size_t)(chunk0 + (lc >> 1)) * 4096;
    const int shalf = (lc & 1) * 4;    // s offset within the K128 chunk
    for (int u = tid; u < 2048; u += 256) {
        int lane = u & 31, gp = (u >> 5) & 15, sl = (u >> 9) & 3;
        int kb = sl * 16 + (lane & 3) * 2;          // k within this 64-row block
        uint32_t wreg[4];
#pragma unroll
        for (int e = 0; e < 2; e++) {
            int n = (gp * 2 + e) * 8 + (lane >> 2);
            __half2 w0 = __floats2half2_rn(ws[kb * 257 + n],       ws[(kb + 1) * 257 + n]);
            __half2 w1 = __floats2half2_rn(ws[(kb + 8) * 257 + n], ws[(kb + 9) * 257 + n]);
            wreg[e * 2]     = *(uint32_t*)&w0;
            wreg[e * 2 + 1] = *(uint32_t*)&w1;
        }
        g_B[base + (size_t)(((shalf + sl) * 16 + gp) * 32 + lane)] =
            make_uint4(wreg[0], wreg[1], wreg[2], wreg[3]);
    }
}

// =============== cooperative A generation: fp16 into SMEM ==================
// thread tid -> row m = tid/4, k-quarter kq = tid&3 (32 k each = 4 uint4)

// layer 0 (HP=39): scalar f/c walk over fp32 x
__device__ __forceinline__ void gen_A0(
    const float* __restrict__ xsm, uint32_t* __restrict__ Asm,
    int lch, int tid)
{
    const int m = tid >> 2;
    const int k0 = lch * 128 + (tid & 3) * 32;
    int f = k0 / F_DIM, c = k0 - f * F_DIM;
    const float* xrow = xsm + m * XS;
    uint4* dst = (uint4*)(Asm + m * AS + (tid & 3) * 16);
    float xa = xrow[f];
#pragma unroll
    for (int v = 0; v < 4; v++) {
        uint32_t w4[4];
#pragma unroll
        for (int w = 0; w < 4; w++) {
            const int k = k0 + v * 8 + w * 2;
            float a0 = (k < K0_REAL) ? xa * xrow[c] : 0.f;
            if (++c == F_DIM) { c = 0; xa = xrow[++f]; }
            float a1 = (k + 1 < K0_REAL) ? xa * xrow[c] : 0.f;
            if (++c == F_DIM) { c = 0; xa = xrow[++f]; }
            __half2 p = __floats2half2_rn(a0, a1);
            w4[w] = *(uint32_t*)&p;
        }
        dst[v] = make_uint4(w4[0], w4[1], w4[2], w4[3]);
    }
}

// layers 1/2 (HP=128): whole chunk has f == lch; c = kq*32 + ...
__device__ __forceinline__ void gen_A12(
    const float* __restrict__ xsm, const __half* __restrict__ hsm,
    uint32_t* __restrict__ Asm, int lch, int tid)
{
    const int m = tid >> 2;
    const int c0 = (tid & 3) * 32;
    const float xa = xsm[m * XS + lch];
    const uint4* hrow = (const uint4*)(hsm + m * HS2 + c0);
    uint4* dst = (uint4*)(Asm + m * AS + (tid & 3) * 16);
#pragma unroll
    for (int v = 0; v < 4; v++) {
        uint4 hv = hrow[v];
        uint32_t hw[4] = { hv.x, hv.y, hv.z, hv.w };
        uint32_t ow[4];
#pragma unroll
        for (int e = 0; e < 4; e++) {
            float2 hf = __half22float2(*(__half2*)&hw[e]);
            __half2 p = __floats2half2_rn(xa * hf.x, xa * hf.y);
            ow[e] = *(uint32_t*)&p;
        }
        dst[v] = make_uint4(ow[0], ow[1], ow[2], ow[3]);
    }
}

// ===================== per-chunk MMA (one K128 chunk) ======================
// warp grid 2M x 4N: wm in [0,2) -> 32-row tile (2 mt x 16);
//                    wn in [0,4) -> 64-col tile.  B straight from L2 via LDG.
__device__ __forceinline__ void chunk_mma(
    uint32_t abase, const uint4* __restrict__ gb, int lane, int wm, int wn,
    float (&acc)[2][8][4])
{
    const int mtx = lane >> 3, rw = lane & 7;
    const uint32_t alane = abase
        + (uint32_t)((wm * 32 + rw + (mtx & 1) * 8) * 272)
        + (uint32_t)((mtx >> 1) * 16);
    const uint4* gbl = gb + (wn * 4) * 32 + lane;

#pragma unroll
    for (int s = 0; s < 8; s++) {
        uint4 bv[4];
        uint32_t afr[2][4];
#pragma unroll
        for (int g = 0; g < 4; g++)
            bv[g] = __ldg(gbl + (s * 16 + g) * 32);
#pragma unroll
        for (int mt = 0; mt < 2; mt++)
            ldmx4(afr[mt], alane + s * 32 + mt * (16 * 272));
#pragma unroll
        for (int g = 0; g < 4; g++)
#pragma unroll
            for (int mt = 0; mt < 2; mt++) {
                mma_f16(acc[mt][g * 2],     afr[mt], bv[g].x, bv[g].y);
                mma_f16(acc[mt][g * 2 + 1], afr[mt], bv[g].z, bv[g].w);
            }
    }
}

// ============================ main fused kernel ============================
__global__ void __launch_bounds__(NT, 2)
cin_mma(const float* __restrict__ x,
        const float* __restrict__ b0, const float* __restrict__ b1,
        const float* __restrict__ b2,
        const float* __restrict__ fcw, const float* __restrict__ fcb,
        float* __restrict__ out)
{
    extern __shared__ char sm[];
    const uint32_t smb = s2u(sm);
    float* xsm = (float*)(sm + SM_X);
    __half* hsm = (__half*)(sm + SM_H);
    float* rowsum = (float*)(sm + SM_RS);

    const int tid = threadIdx.x, wid = tid >> 5, lane = tid & 31;
    const int wm = wid & 1, wn = wid >> 1;
    const int m0 = blockIdx.x * MT;

    if (tid < MT) rowsum[tid] = 0.f;

    // stage x tile: xsm[ml][f] = x[b, f, d];  m = m0+ml
    for (int i = tid; i < F_DIM * MT; i += NT) {
        int f = i >> 6, ml = i & 63, m = m0 + ml;
        xsm[ml * XS + f] = x[((size_t)(m >> 5) * F_DIM + f) * 32 + (m & 31)];
    }
    __syncthreads();    // x ready

    float acc[2][8][4];
    int gch = 0;

    for (int L = 0; L < 3; L++) {
        const int nch = (L == 0) ? NCH0 : NCH12;
#pragma unroll
        for (int mt = 0; mt < 2; mt++)
#pragma unroll
            for (int j = 0; j < 8; j++)
#pragma unroll
                for (int r = 0; r < 4; r++) acc[mt][j][r] = 0.f;

        for (int lch = 0; lch < nch; lch++, gch++) {
            const uint32_t ab = smb + SM_A + (gch & 1) * A_BUF;

            // gen A(gch) into buffer gch&1.  Safe vs mma(gch-1): that reads
            // buffer (gch-1)&1.  Safe vs mma(gch-2) readers of this buffer:
            // all warps passed sync(gch-1) only after finishing mma(gch-2).
            if (L == 0) gen_A0(xsm, (uint32_t*)(sm + SM_A + (gch & 1) * A_BUF), lch, tid);
            else        gen_A12(xsm, hsm, (uint32_t*)(sm + SM_A + (gch & 1) * A_BUF), lch, tid);

            __syncthreads();    // A(gch) visible to all warps

            chunk_mma(ab, g_B + (size_t)gch * 4096, lane, wm, wn, acc);
            // no trailing barrier; warps drift until next chunk's sync
        }

        // ---- layer epilogue: bias+relu, h feedback (fp16), fc_w dots ----
        const float* bias = (L == 0) ? b0 : (L == 1) ? b1 : b2;
        const float* fa   = (L == 0) ? (fcw - 128) : (L == 1) ? fcw : (fcw + 256);
        const int cs      = (L < 2) ? 128 : 0;
        const bool wh     = (L < 2);
        float rs[4] = {0.f, 0.f, 0.f, 0.f};
#pragma unroll
        for (int mt = 0; mt < 2; mt++)
#pragma unroll
            for (int j = 0; j < 8; j++)
#pragma unroll
                for (int r = 0; r < 4; r++) {
                    int row = wm * 32 + mt * 16 + (lane >> 2) + ((r >> 1) << 3);
                    int col = wn * 64 + j * 8 + ((lane & 3) << 1) + (r & 1);
                    float v = fmaxf(acc[mt][j][r] + __ldg(&bias[col]), 0.f);
                    if (wh && col < 128) hsm[row * HS2 + col] = __float2half(v);
                    if (col >= cs) rs[mt * 2 + (r >> 1)] += v * __ldg(&fa[col]);
                }
#pragma unroll
        for (int i = 0; i < 4; i++) {
            float v = rs[i];
            v += __shfl_xor_sync(0xffffffffu, v, 1);
            v += __shfl_xor_sync(0xffffffffu, v, 2);
            if ((lane & 3) == 0) {
                int row = wm * 32 + (i >> 1) * 16 + (lane >> 2) + ((i & 1) << 3);
                atomicAdd(&rowsum[row], v);
            }
        }
        __syncthreads();    // h + rowsum complete before next layer's gen
    }

    // final: each 32-row group (= one batch element) reduces to one scalar
    if (tid < MT) {
        float v = rowsum[tid];
#pragma unroll
        for (int o = 16; o; o >>= 1) v += __shfl_xor_sync(0xffffffffu, v, o);
        if ((tid & 31) == 0) out[blockIdx.x * 2 + wid] = v + fcb[0];
    }
}

// ============================ launch =======================================
extern "C" void kernel_launch(void* const* d_in, const int* in_sizes, int n_in,
                              void* d_out, int out_size)
{
    const float* x   = (const float*)d_in[0];
    const float* W0  = (const float*)d_in[1];
    const float* b0  = (const float*)d_in[2];
    const float* W1  = (const float*)d_in[3];
    const float* b1  = (const float*)d_in[4];
    const float* W2  = (const float*)d_in[5];
    const float* b2  = (const float*)d_in[6];
    const float* fcw = (const float*)d_in[7];
    const float* fcb = (const float*)d_in[8];
    float* out = (float*)d_out;

    // weight shuffle/convert (every launch; idempotent, graph-capturable)
    const int conv_smem = 64 * 257 * 4;
    cudaFuncSetAttribute(conv_kernel, cudaFuncAttributeMaxDynamicSharedMemorySize, conv_smem);
    conv_kernel<<<24, 256, conv_smem>>>(W0, K0_REAL, 0);            // chunks 0..11
    conv_kernel<<<78, 256, conv_smem>>>(W1, 4992, NCH0);            // chunks 12..50
    conv_kernel<<<78, 256, conv_smem>>>(W2, 4992, NCH0 + NCH12);    // chunks 51..89

    int B = in_sizes[0] / (F_DIM * 32);      // 1024
    int grid = (B * 32) / MT;                // 512

    cudaFuncSetAttribute(cin_mma, cudaFuncAttributeMaxDynamicSharedMemorySize, SM_TOT);
    cin_mma<<<grid, NT, SM_TOT>>>(x, b0, b1, b2, fcw, fcb, out);
}